// round 5
// baseline (speedup 1.0000x reference)
#include <cuda_runtime.h>

// LSTMNextWindowPredictor: B=262144 sequences, T=5, I=13, H=64, O=13.
// One thread per batch element. Weights staged in shared memory (broadcast
// reads). h kept in registers (statically indexed, fully unrolled k-loop);
// c / h-next staged in per-thread shared-memory columns (dynamic j index).
// Pure fp32 math; activations via MUFU ex2/rcp approx (rel err ~2^-21).

#define TT 5
#define II 13
#define HH 64
#define OO 13
#define G4 (4 * HH)
#define BLK 256

__device__ __forceinline__ float fexp_(float x) {
    float y;
    asm("ex2.approx.ftz.f32 %0, %1;" : "=f"(y) : "f"(x * 1.4426950408889634f));
    return y;
}
__device__ __forceinline__ float frcp_(float x) {
    float y;
    asm("rcp.approx.ftz.f32 %0, %1;" : "=f"(y) : "f"(x));
    return y;
}
__device__ __forceinline__ float sigmoid_(float x) {
    return frcp_(1.0f + fexp_(-x));
}
__device__ __forceinline__ float tanh_(float x) {
    // tanh(x) = 1 - 2/(e^{2x}+1); saturates correctly for |x| large.
    float e = fexp_(2.0f * x);
    return 1.0f - 2.0f * frcp_(e + 1.0f);
}

extern __shared__ float smem[];

__global__ __launch_bounds__(BLK, 1)
void lstm_mlp_kernel(const float* __restrict__ x,
                     const float* __restrict__ W_ih,
                     const float* __restrict__ W_hh,
                     const float* __restrict__ b_ih,
                     const float* __restrict__ b_hh,
                     const float* __restrict__ W1,
                     const float* __restrict__ b1,
                     const float* __restrict__ W2,
                     const float* __restrict__ b2,
                     float* __restrict__ out,
                     int B) {
    // shared layout
    float* sWhh = smem;                  // G4*HH  = 16384 floats
    float* sWih = sWhh + G4 * HH;        // G4*II  = 3328
    float* sBC  = sWih + G4 * II;        // G4     = 256
    float* sH   = sBC + G4;              // HH*BLK = 16384
    float* sC   = sH + HH * BLK;         // HH*BLK = 16384

    const int tid = threadIdx.x;

    // cooperative, coalesced weight staging
    for (int i = tid; i < G4 * HH; i += BLK) sWhh[i] = W_hh[i];
    for (int i = tid; i < G4 * II; i += BLK) sWih[i] = W_ih[i];
    for (int i = tid; i < G4; i += BLK) sBC[i] = b_ih[i] + b_hh[i];
    __syncthreads();

    const long b = (long)blockIdx.x * BLK + tid;
    const bool active = (b < (long)B);
    const float* xp = x + b * (long)(TT * II);

    // recurrent state: h in registers (static indexing only), c in smem column
    float hr[HH];
#pragma unroll
    for (int k = 0; k < HH; k++) hr[k] = 0.0f;
#pragma unroll
    for (int j = 0; j < HH; j++) sC[j * BLK + tid] = 0.0f;

    for (int t = 0; t < TT; t++) {
        float xr[II];
#pragma unroll
        for (int i = 0; i < II; i++)
            xr[i] = active ? __ldg(xp + t * II + i) : 0.0f;

#pragma unroll 1
        for (int j = 0; j < HH; j++) {
            float ai = sBC[j];
            float af = sBC[HH + j];
            float ag = sBC[2 * HH + j];
            float ao = sBC[3 * HH + j];

            const float* wxi = sWih + j * II;
            const float* wxf = sWih + (HH + j) * II;
            const float* wxg = sWih + (2 * HH + j) * II;
            const float* wxo = sWih + (3 * HH + j) * II;
#pragma unroll
            for (int i = 0; i < II; i++) {
                float xv = xr[i];
                ai += xv * wxi[i];
                af += xv * wxf[i];
                ag += xv * wxg[i];
                ao += xv * wxo[i];
            }

            const float4* whi = reinterpret_cast<const float4*>(sWhh + j * HH);
            const float4* whf = reinterpret_cast<const float4*>(sWhh + (HH + j) * HH);
            const float4* whg = reinterpret_cast<const float4*>(sWhh + (2 * HH + j) * HH);
            const float4* who = reinterpret_cast<const float4*>(sWhh + (3 * HH + j) * HH);
#pragma unroll
            for (int kk = 0; kk < HH / 4; kk++) {
                float4 wa = whi[kk];
                float4 wb = whf[kk];
                float4 wc = whg[kk];
                float4 wd = who[kk];
                float h0 = hr[4 * kk + 0];
                float h1 = hr[4 * kk + 1];
                float h2 = hr[4 * kk + 2];
                float h3 = hr[4 * kk + 3];
                ai += h0 * wa.x; af += h0 * wb.x; ag += h0 * wc.x; ao += h0 * wd.x;
                ai += h1 * wa.y; af += h1 * wb.y; ag += h1 * wc.y; ao += h1 * wd.y;
                ai += h2 * wa.z; af += h2 * wb.z; ag += h2 * wc.z; ao += h2 * wd.z;
                ai += h3 * wa.w; af += h3 * wb.w; ag += h3 * wc.w; ao += h3 * wd.w;
            }

            float si = sigmoid_(ai);
            float sf = sigmoid_(af);
            float so = sigmoid_(ao);
            float tg = tanh_(ag);

            float cold = sC[j * BLK + tid];
            float cn = sf * cold + si * tg;
            sC[j * BLK + tid] = cn;
            sH[j * BLK + tid] = so * tanh_(cn);
        }

        // pull new h back into registers (same-thread smem, no barrier needed)
#pragma unroll
        for (int k = 0; k < HH; k++) hr[k] = sH[k * BLK + tid];
    }

    // ---- MLP head: z = relu(h @ W1^T + b1); out = z @ W2^T + b2 ----
    // W1/W2/biases read via __ldg (broadcast, L1-resident).
#pragma unroll 1
    for (int j = 0; j < HH; j++) {
        float acc = __ldg(b1 + j);
        const float4* w = reinterpret_cast<const float4*>(W1 + j * HH);
#pragma unroll
        for (int kk = 0; kk < HH / 4; kk++) {
            float4 wv = __ldg(w + kk);
            acc += hr[4 * kk + 0] * wv.x;
            acc += hr[4 * kk + 1] * wv.y;
            acc += hr[4 * kk + 2] * wv.z;
            acc += hr[4 * kk + 3] * wv.w;
        }
        sH[j * BLK + tid] = fmaxf(acc, 0.0f);
    }

    float zr[HH];
#pragma unroll
    for (int k = 0; k < HH; k++) zr[k] = sH[k * BLK + tid];

    if (active) {
#pragma unroll
        for (int r = 0; r < OO; r++) {
            float acc = __ldg(b2 + r);
            const float4* w = reinterpret_cast<const float4*>(W2 + r * HH);
#pragma unroll
            for (int kk = 0; kk < HH / 4; kk++) {
                float4 wv = __ldg(w + kk);
                acc += zr[4 * kk + 0] * wv.x;
                acc += zr[4 * kk + 1] * wv.y;
                acc += zr[4 * kk + 2] * wv.z;
                acc += zr[4 * kk + 3] * wv.w;
            }
            out[b * OO + r] = acc;
        }
    }
}

extern "C" void kernel_launch(void* const* d_in, const int* in_sizes, int n_in,
                              void* d_out, int out_size) {
    const float* x    = (const float*)d_in[0];
    const float* W_ih = (const float*)d_in[1];
    const float* W_hh = (const float*)d_in[2];
    const float* b_ih = (const float*)d_in[3];
    const float* b_hh = (const float*)d_in[4];
    const float* W1   = (const float*)d_in[5];
    const float* b1   = (const float*)d_in[6];
    const float* W2   = (const float*)d_in[7];
    const float* b2   = (const float*)d_in[8];
    float* out = (float*)d_out;

    const int B = in_sizes[0] / (TT * II);

    const int smem_bytes =
        (G4 * HH + G4 * II + G4 + HH * BLK + HH * BLK) * (int)sizeof(float);

    static int attr_set = 0;
    if (!attr_set) {
        cudaFuncSetAttribute(lstm_mlp_kernel,
                             cudaFuncAttributeMaxDynamicSharedMemorySize,
                             smem_bytes);
        attr_set = 1;
    }

    const int grid = (B + BLK - 1) / BLK;
    lstm_mlp_kernel<<<grid, BLK, smem_bytes>>>(x, W_ih, W_hh, b_ih, b_hh,
                                               W1, b1, W2, b2, out, B);
}

// round 13
// speedup vs baseline: 1.2933x; 1.2933x over previous
#include <cuda_runtime.h>

// LSTMNextWindowPredictor: B=262144, T=5, I=13, H=64, O=13.
// One thread per batch element. R9 = R6 design with the input-loop bound fixed:
//  * fma.rn.f32x2 (FFMA2) pairing over k: packed h = 2 adjacent regs,
//    packed weights = natural row-major float pairs, 2 partial sums/gate.
//  * W_ih rows padded 13->16 in smem, read as 4 x ulonglong2 (16 floats) --
//    R6/R8 read only 2 x ulonglong2 (8 floats), dropping x[8..12]: rel_err 0.128.
//  * biases packed as float4 per j.
//  * h/z smem readback via __builtin_memcpy (defined aliasing, lowers to LDS.64).
// Weights broadcast from smem; h in registers; c + h-staging in per-thread
// smem columns. Pure fp32; activations via MUFU ex2/rcp (rel err ~2^-21).

#define TT 5
#define II 13
#define HH 64
#define OO 13
#define G4 (4 * HH)
#define BLK 256

typedef unsigned long long u64;

__device__ __forceinline__ u64 pk2(float lo, float hi) {
    u64 r;
    asm("mov.b64 %0, {%1, %2};" : "=l"(r) : "f"(lo), "f"(hi));
    return r;
}
__device__ __forceinline__ void upk2(u64 v, float& lo, float& hi) {
    asm("mov.b64 {%0, %1}, %2;" : "=f"(lo), "=f"(hi) : "l"(v));
}
__device__ __forceinline__ void ffma2(u64& d, u64 a, u64 b) {
    asm("fma.rn.f32x2 %0, %1, %2, %0;" : "+l"(d) : "l"(a), "l"(b));
}

__device__ __forceinline__ float fexp_(float x) {
    float y;
    asm("ex2.approx.ftz.f32 %0, %1;" : "=f"(y) : "f"(x * 1.4426950408889634f));
    return y;
}
__device__ __forceinline__ float frcp_(float x) {
    float y;
    asm("rcp.approx.ftz.f32 %0, %1;" : "=f"(y) : "f"(x));
    return y;
}
__device__ __forceinline__ float sigmoid_(float x) {
    return frcp_(1.0f + fexp_(-x));
}
__device__ __forceinline__ float tanh_(float x) {
    float e = fexp_(2.0f * x);
    return 1.0f - 2.0f * frcp_(e + 1.0f);
}

extern __shared__ float smem[];

__global__ __launch_bounds__(BLK, 1)
void lstm_mlp_kernel(const float* __restrict__ x,
                     const float* __restrict__ W_ih,
                     const float* __restrict__ W_hh,
                     const float* __restrict__ b_ih,
                     const float* __restrict__ b_hh,
                     const float* __restrict__ W1,
                     const float* __restrict__ b1,
                     const float* __restrict__ W2,
                     const float* __restrict__ b2,
                     float* __restrict__ out,
                     int B) {
    // shared layout (all 16B-aligned region boundaries)
    float* sWhh  = smem;                    // G4*HH  = 16384 floats
    float* sWihP = sWhh + G4 * HH;          // G4*16  = 4096
    float* sB4   = sWihP + G4 * 16;         // HH*4   = 256
    float* sH    = sB4 + HH * 4;            // HH*BLK = 16384 (float2-interleaved per thread)
    float* sC    = sH + HH * BLK;           // HH*BLK = 16384

    const int tid = threadIdx.x;

    // cooperative staging
    for (int i = tid; i < G4 * HH; i += BLK) sWhh[i] = W_hh[i];
    for (int i = tid; i < G4 * 16; i += BLK) {
        int row = i >> 4, col = i & 15;
        sWihP[i] = (col < II) ? W_ih[row * II + col] : 0.0f;
    }
    for (int i = tid; i < G4; i += BLK) {
        int g = i & 3, j = i >> 2;                 // sB4[j*4 + g]
        sB4[i] = b_ih[g * HH + j] + b_hh[g * HH + j];
    }
    __syncthreads();

    const long b = (long)blockIdx.x * BLK + tid;
    const bool active = (b < (long)B);
    const float* xp = x + b * (long)(TT * II);

    // h state: 32 packed f32x2 regs (k pairs); c in per-thread smem column
    u64 hr2[HH / 2];
#pragma unroll
    for (int k = 0; k < HH / 2; k++) hr2[k] = 0ull;
#pragma unroll
    for (int j = 0; j < HH; j++) sC[j * BLK + tid] = 0.0f;

    for (int t = 0; t < TT; t++) {
        // x_t padded to 16 and pre-packed as f32x2 pairs
        u64 xr2[8];
#pragma unroll
        for (int q = 0; q < 8; q++) {
            float lo = (2 * q     < II && active) ? __ldg(xp + t * II + 2 * q)     : 0.0f;
            float hi = (2 * q + 1 < II && active) ? __ldg(xp + t * II + 2 * q + 1) : 0.0f;
            xr2[q] = pk2(lo, hi);
        }

#pragma unroll 1
        for (int j = 0; j < HH; j++) {
            const float4 b4 = *reinterpret_cast<const float4*>(sB4 + 4 * j);
            u64 a_i = pk2(b4.x, 0.0f);
            u64 a_f = pk2(b4.y, 0.0f);
            u64 a_g = pk2(b4.z, 0.0f);
            u64 a_o = pk2(b4.w, 0.0f);

            // input contribution: 16 padded floats/gate = 4 x ulonglong2 each
            // (each ulonglong2 = 4 floats; R6/R8 bug was q < 2 here)
            {
                const ulonglong2* wi = reinterpret_cast<const ulonglong2*>(sWihP + j * 16);
                const ulonglong2* wf = reinterpret_cast<const ulonglong2*>(sWihP + (HH + j) * 16);
                const ulonglong2* wg = reinterpret_cast<const ulonglong2*>(sWihP + (2 * HH + j) * 16);
                const ulonglong2* wo = reinterpret_cast<const ulonglong2*>(sWihP + (3 * HH + j) * 16);
#pragma unroll
                for (int q = 0; q < 4; q++) {
                    ulonglong2 vi = wi[q], vf = wf[q], vg = wg[q], vo = wo[q];
                    u64 x0 = xr2[2 * q], x1 = xr2[2 * q + 1];
                    ffma2(a_i, x0, vi.x); ffma2(a_i, x1, vi.y);
                    ffma2(a_f, x0, vf.x); ffma2(a_f, x1, vf.y);
                    ffma2(a_g, x0, vg.x); ffma2(a_g, x1, vg.y);
                    ffma2(a_o, x0, vo.x); ffma2(a_o, x1, vo.y);
                }
            }

            // recurrent contribution: 64 floats/gate = 16 x ulonglong2 each
            {
                const ulonglong2* wi = reinterpret_cast<const ulonglong2*>(sWhh + j * HH);
                const ulonglong2* wf = reinterpret_cast<const ulonglong2*>(sWhh + (HH + j) * HH);
                const ulonglong2* wg = reinterpret_cast<const ulonglong2*>(sWhh + (2 * HH + j) * HH);
                const ulonglong2* wo = reinterpret_cast<const ulonglong2*>(sWhh + (3 * HH + j) * HH);
#pragma unroll
                for (int q = 0; q < 16; q++) {
                    ulonglong2 vi = wi[q], vf = wf[q], vg = wg[q], vo = wo[q];
                    u64 h0 = hr2[2 * q], h1 = hr2[2 * q + 1];
                    ffma2(a_i, h0, vi.x); ffma2(a_i, h1, vi.y);
                    ffma2(a_f, h0, vf.x); ffma2(a_f, h1, vf.y);
                    ffma2(a_g, h0, vg.x); ffma2(a_g, h1, vg.y);
                    ffma2(a_o, h0, vo.x); ffma2(a_o, h1, vo.y);
                }
            }

            float l0, h0, l1, h1, l2, h2, l3, h3;
            upk2(a_i, l0, h0); upk2(a_f, l1, h1);
            upk2(a_g, l2, h2); upk2(a_o, l3, h3);
            float ai = l0 + h0, af = l1 + h1, ag = l2 + h2, ao = l3 + h3;

            float si = sigmoid_(ai);
            float sf = sigmoid_(af);
            float so = sigmoid_(ao);
            float tg = tanh_(ag);

            float cold = sC[j * BLK + tid];
            float cn = sf * cold + si * tg;
            sC[j * BLK + tid] = cn;
            // float2-interleaved per-thread layout so readback is LDS.64 pairs
            sH[(j & ~1) * BLK + 2 * tid + (j & 1)] = so * tanh_(cn);
        }

        // pull new h back as packed pairs (same-thread smem, no barrier)
#pragma unroll
        for (int q = 0; q < HH / 2; q++) {
            u64 v;
            __builtin_memcpy(&v, sH + q * 2 * BLK + 2 * tid, 8);
            hr2[q] = v;
        }
    }

    // ---- MLP head: z = relu(h @ W1^T + b1); out = z @ W2^T + b2 ----
#pragma unroll 1
    for (int j = 0; j < HH; j++) {
        u64 acc = pk2(__ldg(b1 + j), 0.0f);
        const ulonglong2* w = reinterpret_cast<const ulonglong2*>(W1 + j * HH);
#pragma unroll
        for (int q = 0; q < 16; q++) {
            ulonglong2 wv = __ldg(w + q);
            ffma2(acc, hr2[2 * q], wv.x);
            ffma2(acc, hr2[2 * q + 1], wv.y);
        }
        float lo, hi;
        upk2(acc, lo, hi);
        sH[(j & ~1) * BLK + 2 * tid + (j & 1)] = fmaxf(lo + hi, 0.0f);
    }

    u64 zr2[HH / 2];
#pragma unroll
    for (int q = 0; q < HH / 2; q++) {
        u64 v;
        __builtin_memcpy(&v, sH + q * 2 * BLK + 2 * tid, 8);
        zr2[q] = v;
    }

    if (active) {
#pragma unroll
        for (int r = 0; r < OO; r++) {
            u64 acc = pk2(__ldg(b2 + r), 0.0f);
            const ulonglong2* w = reinterpret_cast<const ulonglong2*>(W2 + r * HH);
#pragma unroll
            for (int q = 0; q < 16; q++) {
                ulonglong2 wv = __ldg(w + q);
                ffma2(acc, zr2[2 * q], wv.x);
                ffma2(acc, zr2[2 * q + 1], wv.y);
            }
            float lo, hi;
            upk2(acc, lo, hi);
            out[b * OO + r] = lo + hi;
        }
    }
}

extern "C" void kernel_launch(void* const* d_in, const int* in_sizes, int n_in,
                              void* d_out, int out_size) {
    const float* x    = (const float*)d_in[0];
    const float* W_ih = (const float*)d_in[1];
    const float* W_hh = (const float*)d_in[2];
    const float* b_ih = (const float*)d_in[3];
    const float* b_hh = (const float*)d_in[4];
    const float* W1   = (const float*)d_in[5];
    const float* b1   = (const float*)d_in[6];
    const float* W2   = (const float*)d_in[7];
    const float* b2   = (const float*)d_in[8];
    float* out = (float*)d_out;

    const int B = in_sizes[0] / (TT * II);

    const int smem_bytes =
        (G4 * HH + G4 * 16 + HH * 4 + HH * BLK + HH * BLK) * (int)sizeof(float);

    static int attr_set = 0;
    if (!attr_set) {
        cudaFuncSetAttribute(lstm_mlp_kernel,
                             cudaFuncAttributeMaxDynamicSharedMemorySize,
                             smem_bytes);
        attr_set = 1;
    }

    const int grid = (B + BLK - 1) / BLK;
    lstm_mlp_kernel<<<grid, BLK, smem_bytes>>>(x, W_ih, W_hh, b_ih, b_hh,
                                               W1, b1, W2, b2, out, B);
}